// round 2
// baseline (speedup 1.0000x reference)
#include <cuda_runtime.h>

// ============================================================================
// QFCModel: 4-qubit / 3-layer variational circuit + Linear(4,4) + BatchNorm1d
//
//   out_j(sample) = sum_{k in {0,1,2}^4} C_j[k] * prod_i b_i[k_i],
//   b_i = (1, cos t_i, sin t_i),  t_i = 2*pi*(x_i - mn)*inv_range
//
// C_j (4 x 81) is obtained EXACTLY by simulating the reference circuit at the
// 81 probe points t_i in {0, pi/2, pi} (one thread per probe, 16-amplitude
// state-vector sim) and applying per-mode inverse transforms:
//   f = A + B cos t + C sin t:  A=(f0+f2)/2, B=(f0-f2)/2, C=f1-A.
// Coefficients then go to __constant__ so the hot loop reads them via the
// uniform (LDCU) path and stays FFMA-issue-bound.
// ============================================================================

#define MM_BLOCKS 256

static __constant__ float c_C[328];   // [4][81] coeffs, [324]=mn, [325]=scale

__device__ float  g_C[328];
__device__ float  g_bmin[MM_BLOCKS];
__device__ float  g_bmax[MM_BLOCKS];
__device__ double g_acc[8];           // sum[4], sumsq[4]

// ---------------------------------------------------------------------------
// Phase 1: per-block min/max partials over x[:, :4]
// ---------------------------------------------------------------------------
__global__ void __launch_bounds__(256) k_minmax(const float4* __restrict__ x4, int B) {
    int tid = blockIdx.x * blockDim.x + threadIdx.x;
    int stride = gridDim.x * blockDim.x;
    float mn = 3.402823e38f, mx = -3.402823e38f;
    for (int s = tid; s < B; s += stride) {
        float4 v = __ldg(x4 + (size_t)s * 4);   // row stride = 16 floats
        mn = fminf(mn, fminf(fminf(v.x, v.y), fminf(v.z, v.w)));
        mx = fmaxf(mx, fmaxf(fmaxf(v.x, v.y), fmaxf(v.z, v.w)));
    }
    #pragma unroll
    for (int o = 16; o > 0; o >>= 1) {
        mn = fminf(mn, __shfl_xor_sync(0xffffffffu, mn, o));
        mx = fmaxf(mx, __shfl_xor_sync(0xffffffffu, mx, o));
    }
    __shared__ float smn[8], smx[8];
    int w = threadIdx.x >> 5;
    if ((threadIdx.x & 31) == 0) { smn[w] = mn; smx[w] = mx; }
    __syncthreads();
    if (threadIdx.x == 0) {
        float a = smn[0], b = smx[0];
        #pragma unroll
        for (int i = 1; i < 8; ++i) { a = fminf(a, smn[i]); b = fmaxf(b, smx[i]); }
        g_bmin[blockIdx.x] = a;
        g_bmax[blockIdx.x] = b;
    }
}

// ---------------------------------------------------------------------------
// Phase 2 (1 block, 128 threads): probe-grid coefficient construction.
// Thread t < 81 simulates the circuit at probe point with digits
// g_i = base-3 digits of t (wire 0 = most significant, stride 27),
// t_i = {0, pi/2, pi}[g_i]. Amplitude index a: wire i at bit (3-i).
// ---------------------------------------------------------------------------
__global__ void __launch_bounds__(128) k_precompute(const float* __restrict__ w,
                                                    const float* __restrict__ fcw,
                                                    const float* __restrict__ fcb) {
    __shared__ float E[4][81];
    __shared__ float F[4][81];
    __shared__ float tc[24], ts[24];
    __shared__ float sfw[16], sfb[4];

    int t = threadIdx.x;
    if (t < 24) { float a = 0.5f * w[t]; tc[t] = cosf(a); ts[t] = sinf(a); }
    if (t < 16) sfw[t] = fcw[t];
    if (t < 4)  sfb[t] = fcb[t];
    __syncthreads();

    if (t < 81) {
        int gd[4];
        gd[0] = t / 27; gd[1] = (t / 9) % 3; gd[2] = (t / 3) % 3; gd[3] = t % 3;
        // half-angle (cos,sin) of t/2 for t in {0, pi/2, pi}
        const float encc[3] = {1.0f, 0.70710678118654752f, 0.0f};
        const float encs[3] = {0.0f, 0.70710678118654752f, 1.0f};

        float ar[16], ai[16];
        #pragma unroll
        for (int a = 0; a < 16; ++a) { ar[a] = 0.0f; ai[a] = 0.0f; }
        ar[0] = 1.0f;

        // input-encoding RYs
        #pragma unroll
        for (int i = 0; i < 4; ++i) {
            int m = 8 >> i;
            float c = encc[gd[i]], s = encs[gd[i]];
            #pragma unroll
            for (int a = 0; a < 16; ++a) {
                if (a & m) continue;
                float x0r = ar[a],     x0i = ai[a];
                float x1r = ar[a | m], x1i = ai[a | m];
                ar[a]     = c * x0r - s * x1r;  ai[a]     = c * x0i - s * x1i;
                ar[a | m] = s * x0r + c * x1r;  ai[a | m] = s * x0i + c * x1i;
            }
        }
        // ansatz layers
        for (int l = 0; l < 3; ++l) {
            #pragma unroll
            for (int i = 0; i < 4; ++i) {
                int m = 8 >> i;
                int base = (l * 4 + i) * 2;
                float cy = tc[base], sy = ts[base];
                float cz = tc[base + 1], sz = ts[base + 1];
                #pragma unroll
                for (int a = 0; a < 16; ++a) {
                    if (a & m) continue;
                    float x0r = ar[a],     x0i = ai[a];
                    float x1r = ar[a | m], x1i = ai[a | m];
                    // RY
                    float n0r = cy * x0r - sy * x1r, n0i = cy * x0i - sy * x1i;
                    float n1r = sy * x0r + cy * x1r, n1i = sy * x0i + cy * x1i;
                    // RZ: bit0 phase (cz - i sz), bit1 phase (cz + i sz)
                    ar[a]     = cz * n0r + sz * n0i;  ai[a]     = cz * n0i - sz * n0r;
                    ar[a | m] = cz * n1r - sz * n1i;  ai[a | m] = cz * n1i + sz * n1r;
                }
            }
            // CNOT chain (0,1)(1,2)(2,3)(3,0): basis a -> a with q_t ^= q_c
            #pragma unroll
            for (int e = 0; e < 4; ++e) {
                int cwire = e, twire = (e + 1) & 3;
                int mc = 8 >> cwire, mt = 8 >> twire;
                #pragma unroll
                for (int a = 0; a < 16; ++a) {
                    if ((a & mc) && !(a & mt)) {
                        int b = a ^ mt;
                        float vr = ar[a], vi = ai[a];
                        ar[a] = ar[b]; ai[a] = ai[b];
                        ar[b] = vr;    ai[b] = vi;
                    }
                }
            }
        }
        // PauliZ expvals
        float z[4] = {0.f, 0.f, 0.f, 0.f};
        #pragma unroll
        for (int a = 0; a < 16; ++a) {
            float p = ar[a] * ar[a] + ai[a] * ai[a];
            #pragma unroll
            for (int i = 0; i < 4; ++i)
                z[i] += (a & (8 >> i)) ? -p : p;
        }
        #pragma unroll
        for (int j = 0; j < 4; ++j) {
            float o = sfb[j];
            #pragma unroll
            for (int i = 0; i < 4; ++i) o += sfw[j * 4 + i] * z[i];
            E[j][t] = o;
        }
    }
    __syncthreads();

    // Per-mode inverse transforms: evaluations at {0, pi/2, pi} -> (1,cos,sin)
    // coefficients. Strides 27,9,3,1 (wire 0 first). Double-buffered E<->F.
    {
        float (*S)[81] = E; float (*D)[81] = F;
        const int strides[4] = {27, 9, 3, 1};
        #pragma unroll
        for (int mode = 0; mode < 4; ++mode) {
            int st = strides[mode];
            for (int idx = t; idx < 324; idx += 128) {
                int j = idx / 81, g = idx - (idx / 81) * 81;
                int dg = (g / st) % 3;
                if (dg == 0) {
                    float f0 = S[j][g], f1 = S[j][g + st], f2 = S[j][g + 2 * st];
                    float A = 0.5f * (f0 + f2);
                    D[j][g]          = A;               // const
                    D[j][g + st]     = 0.5f * (f0 - f2);// cos coeff
                    D[j][g + 2 * st] = f1 - A;          // sin coeff
                }
            }
            __syncthreads();
            float (*tmp)[81] = S; S = D; D = tmp;
        }
        // after 4 swaps, result is back in E
        for (int idx = t; idx < 324; idx += 128)
            g_C[idx] = E[idx / 81][idx - (idx / 81) * 81];
    }

    // finalize global min / scale
    if (t < 32) {
        float mn = g_bmin[t], mx = g_bmax[t];
        for (int i = t + 32; i < MM_BLOCKS; i += 32) {
            mn = fminf(mn, g_bmin[i]); mx = fmaxf(mx, g_bmax[i]);
        }
        #pragma unroll
        for (int o = 16; o > 0; o >>= 1) {
            mn = fminf(mn, __shfl_xor_sync(0xffffffffu, mn, o));
            mx = fmaxf(mx, __shfl_xor_sync(0xffffffffu, mx, o));
        }
        if (t == 0) {
            g_C[324] = mn;
            g_C[325] = 6.283185307179586f / (mx - mn + 1e-8f);
        }
    }
}

// ---------------------------------------------------------------------------
// Phase 3: main contraction. Per sample: LDG.128 + 4 sincos + 320 FFMA +
// STG.128; coefficients via LDCU. Accumulates per-channel sum / sumsq for BN.
// ---------------------------------------------------------------------------
__global__ void __launch_bounds__(128) k_main(const float4* __restrict__ x4,
                                              float4* __restrict__ out, int B) {
    const float mn = c_C[324], sc = c_C[325];
    float ps0 = 0.f, ps1 = 0.f, ps2 = 0.f, ps3 = 0.f;
    float pq0 = 0.f, pq1 = 0.f, pq2 = 0.f, pq3 = 0.f;
    int tid = blockIdx.x * blockDim.x + threadIdx.x;
    int stride = gridDim.x * blockDim.x;

    #pragma unroll 1
    for (int s = tid; s < B; s += stride) {
        float4 v = __ldg(x4 + (size_t)s * 4);
        float a0 = (v.x - mn) * sc, a1 = (v.y - mn) * sc;
        float a2 = (v.z - mn) * sc, a3 = (v.w - mn) * sc;
        float s0, c0, s1, c1, s2, c2, s3, c3;
        __sincosf(a0, &s0, &c0); __sincosf(a1, &s1, &c1);
        __sincosf(a2, &s2, &c2); __sincosf(a3, &s3, &c3);

        float o[4];
        #pragma unroll
        for (int j = 0; j < 4; ++j) {
            const float* C = &c_C[j * 81];
            float r1[27];
            #pragma unroll
            for (int k = 0; k < 27; ++k)
                r1[k] = fmaf(c0, C[27 + k], fmaf(s0, C[54 + k], C[k]));
            float r2[9];
            #pragma unroll
            for (int k = 0; k < 9; ++k)
                r2[k] = fmaf(c1, r1[9 + k], fmaf(s1, r1[18 + k], r1[k]));
            float r3[3];
            #pragma unroll
            for (int k = 0; k < 3; ++k)
                r3[k] = fmaf(c2, r2[3 + k], fmaf(s2, r2[6 + k], r2[k]));
            o[j] = fmaf(c3, r3[1], fmaf(s3, r3[2], r3[0]));
        }
        out[s] = make_float4(o[0], o[1], o[2], o[3]);
        ps0 += o[0]; pq0 += o[0] * o[0];
        ps1 += o[1]; pq1 += o[1] * o[1];
        ps2 += o[2]; pq2 += o[2] * o[2];
        ps3 += o[3]; pq3 += o[3] * o[3];
    }

    #pragma unroll
    for (int o = 16; o > 0; o >>= 1) {
        ps0 += __shfl_xor_sync(0xffffffffu, ps0, o);
        ps1 += __shfl_xor_sync(0xffffffffu, ps1, o);
        ps2 += __shfl_xor_sync(0xffffffffu, ps2, o);
        ps3 += __shfl_xor_sync(0xffffffffu, ps3, o);
        pq0 += __shfl_xor_sync(0xffffffffu, pq0, o);
        pq1 += __shfl_xor_sync(0xffffffffu, pq1, o);
        pq2 += __shfl_xor_sync(0xffffffffu, pq2, o);
        pq3 += __shfl_xor_sync(0xffffffffu, pq3, o);
    }
    __shared__ float red[4][8];
    int w = threadIdx.x >> 5;
    if ((threadIdx.x & 31) == 0) {
        red[w][0] = ps0; red[w][1] = ps1; red[w][2] = ps2; red[w][3] = ps3;
        red[w][4] = pq0; red[w][5] = pq1; red[w][6] = pq2; red[w][7] = pq3;
    }
    __syncthreads();
    if (threadIdx.x < 8) {
        float a = red[0][threadIdx.x] + red[1][threadIdx.x] +
                  red[2][threadIdx.x] + red[3][threadIdx.x];
        atomicAdd(&g_acc[threadIdx.x], (double)a);
    }
}

// ---------------------------------------------------------------------------
// Phase 4: BatchNorm (biased var) applied in-place on d_out.
// ---------------------------------------------------------------------------
__global__ void __launch_bounds__(256) k_bn(float4* __restrict__ out,
                                            const float* __restrict__ gamma,
                                            const float* __restrict__ beta,
                                            int B, double invB) {
    float scv[4], shv[4];
    #pragma unroll
    for (int j = 0; j < 4; ++j) {
        double mean = g_acc[j] * invB;
        double var  = g_acc[4 + j] * invB - mean * mean;
        float s = __ldg(&gamma[j]) * rsqrtf((float)var + 1e-5f);
        scv[j] = s;
        shv[j] = __ldg(&beta[j]) - (float)mean * s;
    }
    int tid = blockIdx.x * blockDim.x + threadIdx.x;
    int stride = gridDim.x * blockDim.x;
    for (int s = tid; s < B; s += stride) {
        float4 v = out[s];
        v.x = fmaf(v.x, scv[0], shv[0]);
        v.y = fmaf(v.y, scv[1], shv[1]);
        v.z = fmaf(v.z, scv[2], shv[2]);
        v.w = fmaf(v.w, scv[3], shv[3]);
        out[s] = v;
    }
}

// ---------------------------------------------------------------------------
extern "C" void kernel_launch(void* const* d_in, const int* in_sizes, int n_in,
                              void* d_out, int out_size) {
    const float* x     = (const float*)d_in[0];   // [B,16]
    const float* w     = (const float*)d_in[1];   // [3,4,2]
    const float* fcw   = (const float*)d_in[2];   // [4,4]
    const float* fcb   = (const float*)d_in[3];   // [4]
    const float* gamma = (const float*)d_in[4];   // [4]
    const float* beta  = (const float*)d_in[5];   // [4]
    int B = in_sizes[0] / 16;
    float* out = (float*)d_out;

    void* accp = nullptr;
    cudaGetSymbolAddress(&accp, g_acc);
    cudaMemsetAsync(accp, 0, 8 * sizeof(double));

    k_minmax<<<MM_BLOCKS, 256>>>((const float4*)x, B);
    k_precompute<<<1, 128>>>(w, fcw, fcb);

    void* gcp = nullptr;
    cudaGetSymbolAddress(&gcp, g_C);
    cudaMemcpyToSymbolAsync(c_C, gcp, 328 * sizeof(float), 0,
                            cudaMemcpyDeviceToDevice);

    k_main<<<1024, 128>>>((const float4*)x, (float4*)out, B);
    k_bn<<<256, 256>>>((float4*)out, gamma, beta, B, 1.0 / (double)B);
}